// round 8
// baseline (speedup 1.0000x reference)
#include <cuda_runtime.h>
#include <stdint.h>

#define N_NODES 100000
#define N_EDGES 1600000
#define N_GRAPHS 256

// ---------------- scratch (no allocation allowed -> device globals) ----------
__device__ int   g_deg_out[N_NODES];
__device__ int   g_deg_in[N_NODES];
__device__ float g_norm_src[N_NODES];
__device__ float g_norm_dst[N_NODES];
__device__ int   g_row[N_NODES + 1];            // CSR row offsets (by dst)
__device__ int   g_cur[N_NODES];                // fill cursors
__device__ int   g_csr[N_EDGES];                // src index per CSR slot
__device__ float g_bufA[(size_t)N_NODES * 128];
__device__ float g_bufB[(size_t)N_NODES * 128];
__device__ int   g_flag_idx;                    // 1 = src/dst are int32
__device__ int   g_flag_gid;                    // 1 = graph_id is int32

// ---------------- helpers ----------------------------------------------------
__device__ __forceinline__ int load_idx(const void* p, long long i, int is32) {
    if (is32) return ((const int*)p)[i];
    return (int)(((const long long*)p)[i]);
}

// init: zero degree arrays; block 0 additionally does dtype detection.
// int64 values < 2^31 -> every odd 32-bit word is 0; int32 data -> nonzero.
// src: head window (random values => certain nonzero if int32).
// gid: TAIL window (sorted ascending; head is legitimately zero either way).
__global__ void init_kernel(const unsigned* __restrict__ s,
                            const unsigned* __restrict__ g) {
    int i = blockIdx.x * blockDim.x + threadIdx.x;
    if (i == 0) { g_flag_idx = 0; g_flag_gid = 0; }
    if (i < N_NODES) { g_deg_out[i] = 0; g_deg_in[i] = 0; }
    if (blockIdx.x == 0) {
        int fi = 0, fg = 0;
        for (int j = threadIdx.x; j < 2048; j += 256)
            if ((j & 1) && s[j]) fi = 1;
        for (int j = N_NODES - 2048 + threadIdx.x; j < N_NODES; j += 256)
            if ((j & 1) && g[j]) fg = 1;
        if (fi) g_flag_idx = 1;
        if (fg) g_flag_gid = 1;
    }
}

__global__ void zero_out_kernel(float* p, int n) {
    int i = blockIdx.x * blockDim.x + threadIdx.x;
    if (i < n) p[i] = 0.0f;
}

// ---------------- degrees ----------------------------------------------------
__global__ void deg_kernel(const void* src, const void* dst) {
    int is32 = g_flag_idx;
    long long i = (long long)blockIdx.x * blockDim.x + threadIdx.x;
    long long stride = (long long)gridDim.x * blockDim.x;
    for (; i < N_EDGES; i += stride) {
        atomicAdd(&g_deg_out[load_idx(src, i, is32)], 1);
        atomicAdd(&g_deg_in[load_idx(dst, i, is32)], 1);
    }
}

// single-block: exclusive scan of deg_in -> row offsets/cursors, plus norms
__global__ void scan_norm_kernel() {
    __shared__ int ssum[1024];
    const int CH = (N_NODES + 1023) / 1024;   // 98
    int t = threadIdx.x;
    int lo = t * CH;
    int hi = min(lo + CH, N_NODES);
    int s = 0;
    for (int i = lo; i < hi; i++) {
        int di = g_deg_in[i];
        int doo = g_deg_out[i];
        s += di;
        g_norm_src[i] = (doo > 0) ? rsqrtf((float)doo) : 0.0f;
        g_norm_dst[i] = (di  > 0) ? rsqrtf((float)di)  : 0.0f;
    }
    ssum[t] = s;
    __syncthreads();
    for (int off = 1; off < 1024; off <<= 1) {
        int v = (t >= off) ? ssum[t - off] : 0;
        __syncthreads();
        ssum[t] += v;
        __syncthreads();
    }
    int run = (t > 0) ? ssum[t - 1] : 0;
    for (int i = lo; i < hi; i++) {
        g_row[i] = run;
        g_cur[i] = run;
        run += g_deg_in[i];
    }
    if (t == 1023) g_row[N_NODES] = ssum[1023];
}

__global__ void fill_csr_kernel(const void* src, const void* dst) {
    int is32 = g_flag_idx;
    long long i = (long long)blockIdx.x * blockDim.x + threadIdx.x;
    long long stride = (long long)gridDim.x * blockDim.x;
    for (; i < N_EDGES; i += stride) {
        int d = load_idx(dst, i, is32);
        int pos = atomicAdd(&g_cur[d], 1);
        g_csr[pos] = load_idx(src, i, is32);
    }
}

// ------- CSR gather (64-dim), 4-edge pipelined; optional per-edge src scale --
// out[n] = (sum_e x[src_e] [* norm_src[src_e]]) * norm_dst[n]
template <int SCALE_SRC>
__global__ void gather64_kernel(const float* __restrict__ x,
                                float* __restrict__ out) {
    int warp = (blockIdx.x << 3) | (threadIdx.x >> 5);
    int lane = threadIdx.x & 31;
    if (warp >= N_NODES) return;
    int lo = g_row[warp], hi = g_row[warp + 1];
    float a0 = 0.f, a1 = 0.f, b0 = 0.f, b1 = 0.f;
    float c0 = 0.f, c1 = 0.f, d0 = 0.f, d1 = 0.f;
    int j = lo;
    for (; j + 3 < hi; j += 4) {
        int s0 = g_csr[j], s1 = g_csr[j + 1], s2 = g_csr[j + 2], s3 = g_csr[j + 3];
        float2 v0 = ((const float2*)(x + (size_t)s0 * 64))[lane];
        float2 v1 = ((const float2*)(x + (size_t)s1 * 64))[lane];
        float2 v2 = ((const float2*)(x + (size_t)s2 * 64))[lane];
        float2 v3 = ((const float2*)(x + (size_t)s3 * 64))[lane];
        if (SCALE_SRC) {
            float n0 = g_norm_src[s0], n1 = g_norm_src[s1];
            float n2 = g_norm_src[s2], n3 = g_norm_src[s3];
            a0 = fmaf(v0.x, n0, a0); a1 = fmaf(v0.y, n0, a1);
            b0 = fmaf(v1.x, n1, b0); b1 = fmaf(v1.y, n1, b1);
            c0 = fmaf(v2.x, n2, c0); c1 = fmaf(v2.y, n2, c1);
            d0 = fmaf(v3.x, n3, d0); d1 = fmaf(v3.y, n3, d1);
        } else {
            a0 += v0.x; a1 += v0.y; b0 += v1.x; b1 += v1.y;
            c0 += v2.x; c1 += v2.y; d0 += v3.x; d1 += v3.y;
        }
    }
    for (; j < hi; j++) {
        int s0 = g_csr[j];
        float2 v0 = ((const float2*)(x + (size_t)s0 * 64))[lane];
        if (SCALE_SRC) {
            float n0 = g_norm_src[s0];
            a0 = fmaf(v0.x, n0, a0); a1 = fmaf(v0.y, n0, a1);
        } else { a0 += v0.x; a1 += v0.y; }
    }
    float nd = g_norm_dst[warp];
    float2 r;
    r.x = ((a0 + b0) + (c0 + d0)) * nd;
    r.y = ((a1 + b1) + (c1 + d1)) * nd;
    ((float2*)(out + (size_t)warp * 64))[lane] = r;
}

// ------- CSR gather (128-dim), 4-edge pipelined -----------------------------
__global__ void gather128_kernel(const float* __restrict__ x,
                                 float* __restrict__ out) {
    int warp = (blockIdx.x << 3) | (threadIdx.x >> 5);
    int lane = threadIdx.x & 31;
    if (warp >= N_NODES) return;
    int lo = g_row[warp], hi = g_row[warp + 1];
    float4 A = {0,0,0,0}, B = {0,0,0,0}, C = {0,0,0,0}, D = {0,0,0,0};
    int j = lo;
    for (; j + 3 < hi; j += 4) {
        int s0 = g_csr[j], s1 = g_csr[j + 1], s2 = g_csr[j + 2], s3 = g_csr[j + 3];
        float4 v0 = ((const float4*)(x + (size_t)s0 * 128))[lane];
        float4 v1 = ((const float4*)(x + (size_t)s1 * 128))[lane];
        float4 v2 = ((const float4*)(x + (size_t)s2 * 128))[lane];
        float4 v3 = ((const float4*)(x + (size_t)s3 * 128))[lane];
        A.x += v0.x; A.y += v0.y; A.z += v0.z; A.w += v0.w;
        B.x += v1.x; B.y += v1.y; B.z += v1.z; B.w += v1.w;
        C.x += v2.x; C.y += v2.y; C.z += v2.z; C.w += v2.w;
        D.x += v3.x; D.y += v3.y; D.z += v3.z; D.w += v3.w;
    }
    for (; j < hi; j++) {
        int s0 = g_csr[j];
        float4 v0 = ((const float4*)(x + (size_t)s0 * 128))[lane];
        A.x += v0.x; A.y += v0.y; A.z += v0.z; A.w += v0.w;
    }
    float nd = g_norm_dst[warp];
    float4 r;
    r.x = ((A.x + B.x) + (C.x + D.x)) * nd;
    r.y = ((A.y + B.y) + (C.y + D.y)) * nd;
    r.z = ((A.z + B.z) + (C.z + D.z)) * nd;
    r.w = ((A.w + B.w) + (C.w + D.w)) * nd;
    ((float4*)(out + (size_t)warp * 128))[lane] = r;
}

// final layer gather: epilogue = relu(acc*nd + b3) then pooled atomicAdd
__global__ void gather_pool_kernel(const float* __restrict__ x,
                                   const float* __restrict__ b3,
                                   const void* __restrict__ gid,
                                   float* __restrict__ out) {
    int warp = (blockIdx.x << 3) | (threadIdx.x >> 5);
    int lane = threadIdx.x & 31;
    if (warp >= N_NODES) return;
    int lo = g_row[warp], hi = g_row[warp + 1];
    float a0 = 0.f, a1 = 0.f, b0 = 0.f, b1 = 0.f;
    float c0 = 0.f, c1 = 0.f, d0 = 0.f, d1 = 0.f;
    int j = lo;
    for (; j + 3 < hi; j += 4) {
        int s0 = g_csr[j], s1 = g_csr[j + 1], s2 = g_csr[j + 2], s3 = g_csr[j + 3];
        float2 v0 = ((const float2*)(x + (size_t)s0 * 64))[lane];
        float2 v1 = ((const float2*)(x + (size_t)s1 * 64))[lane];
        float2 v2 = ((const float2*)(x + (size_t)s2 * 64))[lane];
        float2 v3 = ((const float2*)(x + (size_t)s3 * 64))[lane];
        a0 += v0.x; a1 += v0.y; b0 += v1.x; b1 += v1.y;
        c0 += v2.x; c1 += v2.y; d0 += v3.x; d1 += v3.y;
    }
    for (; j < hi; j++) {
        int s0 = g_csr[j];
        float2 v0 = ((const float2*)(x + (size_t)s0 * 64))[lane];
        a0 += v0.x; a1 += v0.y;
    }
    float nd = g_norm_dst[warp];
    float2 bb = ((const float2*)b3)[lane];
    float r0 = fmaxf(fmaf((a0 + b0) + (c0 + d0), nd, bb.x), 0.0f);
    float r1 = fmaxf(fmaf((a1 + b1) + (c1 + d1), nd, bb.y), 0.0f);
    int g = load_idx(gid, warp, g_flag_gid);
    atomicAdd(&out[(size_t)g * 64 + lane * 2],     r0);
    atomicAdd(&out[(size_t)g * 64 + lane * 2 + 1], r1);
}

// ------- GEMM: out = epilogue(m @ W + b); R node-rows per thread, k by 4 -----
// EPI==1: out = relu(acc + b) * norm_src[n]   (mid layers)
// EPI==0: out = acc                            (layer-3 transform-first)
template <int DIN, int DOUT, int R, int EPI>
__global__ void gemm_kernel(const float4* __restrict__ m4,
                            const float* __restrict__ W,
                            const float* __restrict__ b,
                            float* __restrict__ out) {
    constexpr int TY  = 256 / DOUT;
    constexpr int NPB = TY * R;
    constexpr int K4  = DIN / 4;
    __shared__ float4 sm[NPB * K4];
    int tx = threadIdx.x;            // output feature
    int ty = threadIdx.y;
    int tid = ty * DOUT + tx;
    size_t base = (size_t)blockIdx.x * NPB;

    // cooperative contiguous float4 load of NPB node rows
    const float4* src = m4 + base * K4;
#pragma unroll
    for (int i = tid; i < NPB * K4; i += 256) sm[i] = src[i];
    __syncthreads();

    float bias = EPI ? b[tx] : 0.0f;
    float acc[R];
#pragma unroll
    for (int r = 0; r < R; r++) acc[r] = bias;

#pragma unroll 4
    for (int k4 = 0; k4 < K4; k4++) {
        int k = k4 * 4;
        float w0 = W[(k + 0) * DOUT + tx];
        float w1 = W[(k + 1) * DOUT + tx];
        float w2 = W[(k + 2) * DOUT + tx];
        float w3 = W[(k + 3) * DOUT + tx];
#pragma unroll
        for (int r = 0; r < R; r++) {
            float4 v = sm[(ty * R + r) * K4 + k4];
            acc[r] = fmaf(v.x, w0, acc[r]);
            acc[r] = fmaf(v.y, w1, acc[r]);
            acc[r] = fmaf(v.z, w2, acc[r]);
            acc[r] = fmaf(v.w, w3, acc[r]);
        }
    }

#pragma unroll
    for (int r = 0; r < R; r++) {
        size_t n = base + ty * R + r;
        float v = acc[r];
        if (EPI) v = fmaxf(v, 0.0f) * g_norm_src[n];
        out[n * DOUT + tx] = v;
    }
}

// ---------------- launch ------------------------------------------------------
extern "C" void kernel_launch(void* const* d_in, const int* in_sizes, int n_in,
                              void* d_out, int out_size) {
    const float* h        = (const float*)d_in[0];
    const void*  src      = d_in[1];
    const void*  dst      = d_in[2];
    const void*  graph_id = d_in[3];
    const float* W1 = (const float*)d_in[4];
    const float* b1 = (const float*)d_in[5];
    const float* W2 = (const float*)d_in[6];
    const float* b2 = (const float*)d_in[7];
    const float* W3 = (const float*)d_in[8];
    const float* b3 = (const float*)d_in[9];
    float* out = (float*)d_out;

    float *pA, *pB;
    cudaGetSymbolAddress((void**)&pA, g_bufA);
    cudaGetSymbolAddress((void**)&pB, g_bufB);

    // 0: init (+dtype detect)  1: degrees  2: scan+norms  3: CSR fill
    init_kernel<<<(N_NODES + 255) / 256, 256>>>((const unsigned*)src,
                                                (const unsigned*)graph_id);
    deg_kernel<<<2048, 256>>>(src, dst);
    scan_norm_kernel<<<1, 1024>>>();
    fill_csr_kernel<<<2048, 256>>>(src, dst);

    const int GATHER_GRID = (N_NODES + 7) / 8;     // 8 warps/block

    // layer 1: gather(64, per-edge norm_src from raw h) -> gemm 64->128
    gather64_kernel<1><<<GATHER_GRID, 256>>>(h, pB);
    {
        dim3 blk(128, 2);   // NPB = 16
        gemm_kernel<64, 128, 8, 1><<<N_NODES / 16, blk>>>((const float4*)pB, W1, b1, pA);
    }

    // layer 2: gather(128) -> gemm 128->128
    gather128_kernel<<<GATHER_GRID, 256>>>(pA, pB);
    {
        dim3 blk(128, 2);   // NPB = 16
        gemm_kernel<128, 128, 8, 1><<<N_NODES / 16, blk>>>((const float4*)pB, W2, b2, pA);
    }

    // layer 3: transform first (gemm 128->64, no epi), then gather+pool
    {
        dim3 blk(64, 4);    // NPB = 32
        gemm_kernel<128, 64, 8, 0><<<N_NODES / 32, blk>>>((const float4*)pA, W3, nullptr, pB);
    }
    zero_out_kernel<<<(N_GRAPHS * 64 + 255) / 256, 256>>>(out, N_GRAPHS * 64);
    gather_pool_kernel<<<(N_NODES + 7) / 8, 256>>>(pB, b3, graph_id, out);
}

// round 9
// speedup vs baseline: 1.0395x; 1.0395x over previous
#include <cuda_runtime.h>
#include <cuda_fp16.h>
#include <stdint.h>

#define N_NODES 100000
#define N_EDGES 1600000
#define N_GRAPHS 256

// ---------------- scratch (no allocation allowed -> device globals) ----------
__device__ int    g_deg_out[N_NODES];
__device__ int    g_deg_in[N_NODES];
__device__ float  g_norm_src[N_NODES];
__device__ float  g_norm_dst[N_NODES];
__device__ int    g_row[N_NODES + 1];           // CSR row offsets (by dst)
__device__ int    g_cur[N_NODES];               // fill cursors
__device__ int    g_csr[N_EDGES];               // src index per CSR slot
__device__ __half g_h1[(size_t)N_NODES * 128];  // fp16 feature buffer 1
__device__ __half g_h2[(size_t)N_NODES * 128];  // fp16 feature buffer 2
__device__ float  g_bufA[(size_t)N_NODES * 128];// fp32 gather-output buffer
__device__ int    g_flag_idx;                   // 1 = src/dst are int32
__device__ int    g_flag_gid;                   // 1 = graph_id is int32

// ---------------- helpers ----------------------------------------------------
__device__ __forceinline__ int load_idx(const void* p, long long i, int is32) {
    if (is32) return ((const int*)p)[i];
    return (int)(((const long long*)p)[i]);
}

// init: zero degree arrays; block 0 additionally does dtype detection.
// int64 values < 2^31 -> every odd 32-bit word is 0; int32 data -> nonzero.
// src: head window (random values => certain nonzero if int32).
// gid: TAIL window (sorted ascending; head is legitimately zero either way).
__global__ void init_kernel(const unsigned* __restrict__ s,
                            const unsigned* __restrict__ g) {
    int i = blockIdx.x * blockDim.x + threadIdx.x;
    if (i == 0) { g_flag_idx = 0; g_flag_gid = 0; }
    if (i < N_NODES) { g_deg_out[i] = 0; g_deg_in[i] = 0; }
    if (blockIdx.x == 0) {
        int fi = 0, fg = 0;
        for (int j = threadIdx.x; j < 2048; j += 256)
            if ((j & 1) && s[j]) fi = 1;
        for (int j = N_NODES - 2048 + threadIdx.x; j < N_NODES; j += 256)
            if ((j & 1) && g[j]) fg = 1;
        if (fi) g_flag_idx = 1;
        if (fg) g_flag_gid = 1;
    }
}

__global__ void zero_out_kernel(float* p, int n) {
    int i = blockIdx.x * blockDim.x + threadIdx.x;
    if (i < n) p[i] = 0.0f;
}

// ---------------- degrees ----------------------------------------------------
__global__ void deg_kernel(const void* src, const void* dst) {
    int is32 = g_flag_idx;
    long long i = (long long)blockIdx.x * blockDim.x + threadIdx.x;
    long long stride = (long long)gridDim.x * blockDim.x;
    for (; i < N_EDGES; i += stride) {
        atomicAdd(&g_deg_out[load_idx(src, i, is32)], 1);
        atomicAdd(&g_deg_in[load_idx(dst, i, is32)], 1);
    }
}

// single-block: exclusive scan of deg_in -> row offsets/cursors, plus norms
__global__ void scan_norm_kernel() {
    __shared__ int ssum[1024];
    const int CH = (N_NODES + 1023) / 1024;   // 98
    int t = threadIdx.x;
    int lo = t * CH;
    int hi = min(lo + CH, N_NODES);
    int s = 0;
    for (int i = lo; i < hi; i++) {
        int di = g_deg_in[i];
        int doo = g_deg_out[i];
        s += di;
        g_norm_src[i] = (doo > 0) ? rsqrtf((float)doo) : 0.0f;
        g_norm_dst[i] = (di  > 0) ? rsqrtf((float)di)  : 0.0f;
    }
    ssum[t] = s;
    __syncthreads();
    for (int off = 1; off < 1024; off <<= 1) {
        int v = (t >= off) ? ssum[t - off] : 0;
        __syncthreads();
        ssum[t] += v;
        __syncthreads();
    }
    int run = (t > 0) ? ssum[t - 1] : 0;
    for (int i = lo; i < hi; i++) {
        g_row[i] = run;
        g_cur[i] = run;
        run += g_deg_in[i];
    }
    if (t == 1023) g_row[N_NODES] = ssum[1023];
}

__global__ void fill_csr_kernel(const void* src, const void* dst) {
    int is32 = g_flag_idx;
    long long i = (long long)blockIdx.x * blockDim.x + threadIdx.x;
    long long stride = (long long)gridDim.x * blockDim.x;
    for (; i < N_EDGES; i += stride) {
        int d = load_idx(dst, i, is32);
        int pos = atomicAdd(&g_cur[d], 1);
        g_csr[pos] = load_idx(src, i, is32);
    }
}

// ------ prescale: g_h1 = fp16(h * norm_src), 2 elems per thread --------------
__global__ void prescale_kernel(const float* __restrict__ h) {
    int i = blockIdx.x * blockDim.x + threadIdx.x;   // over N_NODES*32
    if (i >= N_NODES * 32) return;
    int n = i >> 5;
    float ns = g_norm_src[n];
    float2 v = ((const float2*)h)[i];
    v.x *= ns; v.y *= ns;
    ((__half2*)g_h1)[i] = __float22half2_rn(v);
}

// ------- CSR gather (64-dim fp16 rows -> fp32 out), 2-edge pipelined ---------
__global__ void gather64h_kernel(const __half* __restrict__ x,
                                 float* __restrict__ out) {
    int warp = (blockIdx.x << 3) | (threadIdx.x >> 5);
    int lane = threadIdx.x & 31;
    if (warp >= N_NODES) return;
    int lo = g_row[warp], hi = g_row[warp + 1];
    float a0 = 0.f, a1 = 0.f, b0 = 0.f, b1 = 0.f;
    int j = lo;
    for (; j + 1 < hi; j += 2) {
        int s0 = g_csr[j], s1 = g_csr[j + 1];
        unsigned u0 = ((const unsigned*)(x + (size_t)s0 * 64))[lane];
        unsigned u1 = ((const unsigned*)(x + (size_t)s1 * 64))[lane];
        float2 v0 = __half22float2(*(__half2*)&u0);
        float2 v1 = __half22float2(*(__half2*)&u1);
        a0 += v0.x; a1 += v0.y;
        b0 += v1.x; b1 += v1.y;
    }
    if (j < hi) {
        int s0 = g_csr[j];
        unsigned u0 = ((const unsigned*)(x + (size_t)s0 * 64))[lane];
        float2 v0 = __half22float2(*(__half2*)&u0);
        a0 += v0.x; a1 += v0.y;
    }
    float nd = g_norm_dst[warp];
    float2 r; r.x = (a0 + b0) * nd; r.y = (a1 + b1) * nd;
    ((float2*)(out + (size_t)warp * 64))[lane] = r;
}

// ------- CSR gather (128-dim fp16 rows -> fp32 out), 2-edge pipelined --------
__global__ void gather128h_kernel(const __half* __restrict__ x,
                                  float* __restrict__ out) {
    int warp = (blockIdx.x << 3) | (threadIdx.x >> 5);
    int lane = threadIdx.x & 31;
    if (warp >= N_NODES) return;
    int lo = g_row[warp], hi = g_row[warp + 1];
    float a0=0.f,a1=0.f,a2=0.f,a3=0.f,b0=0.f,b1=0.f,b2=0.f,b3=0.f;
    int j = lo;
    for (; j + 1 < hi; j += 2) {
        int s0 = g_csr[j], s1 = g_csr[j + 1];
        uint2 u0 = ((const uint2*)(x + (size_t)s0 * 128))[lane];
        uint2 u1 = ((const uint2*)(x + (size_t)s1 * 128))[lane];
        float2 v0a = __half22float2(*(__half2*)&u0.x);
        float2 v0b = __half22float2(*(__half2*)&u0.y);
        float2 v1a = __half22float2(*(__half2*)&u1.x);
        float2 v1b = __half22float2(*(__half2*)&u1.y);
        a0 += v0a.x; a1 += v0a.y; a2 += v0b.x; a3 += v0b.y;
        b0 += v1a.x; b1 += v1a.y; b2 += v1b.x; b3 += v1b.y;
    }
    if (j < hi) {
        int s0 = g_csr[j];
        uint2 u0 = ((const uint2*)(x + (size_t)s0 * 128))[lane];
        float2 v0a = __half22float2(*(__half2*)&u0.x);
        float2 v0b = __half22float2(*(__half2*)&u0.y);
        a0 += v0a.x; a1 += v0a.y; a2 += v0b.x; a3 += v0b.y;
    }
    float nd = g_norm_dst[warp];
    float4 r;
    r.x = (a0 + b0) * nd; r.y = (a1 + b1) * nd;
    r.z = (a2 + b2) * nd; r.w = (a3 + b3) * nd;
    ((float4*)(out + (size_t)warp * 128))[lane] = r;
}

// final layer gather (fp16 rows): relu(acc*nd + b3) then pooled atomicAdd
__global__ void gather_pool_kernel(const __half* __restrict__ x,
                                   const float* __restrict__ b3,
                                   const void* __restrict__ gid,
                                   float* __restrict__ out) {
    int warp = (blockIdx.x << 3) | (threadIdx.x >> 5);
    int lane = threadIdx.x & 31;
    if (warp >= N_NODES) return;
    int lo = g_row[warp], hi = g_row[warp + 1];
    float a0 = 0.f, a1 = 0.f, b0 = 0.f, b1 = 0.f;
    int j = lo;
    for (; j + 1 < hi; j += 2) {
        int s0 = g_csr[j], s1 = g_csr[j + 1];
        unsigned u0 = ((const unsigned*)(x + (size_t)s0 * 64))[lane];
        unsigned u1 = ((const unsigned*)(x + (size_t)s1 * 64))[lane];
        float2 v0 = __half22float2(*(__half2*)&u0);
        float2 v1 = __half22float2(*(__half2*)&u1);
        a0 += v0.x; a1 += v0.y;
        b0 += v1.x; b1 += v1.y;
    }
    if (j < hi) {
        int s0 = g_csr[j];
        unsigned u0 = ((const unsigned*)(x + (size_t)s0 * 64))[lane];
        float2 v0 = __half22float2(*(__half2*)&u0);
        a0 += v0.x; a1 += v0.y;
    }
    float nd = g_norm_dst[warp];
    float2 bb = ((const float2*)b3)[lane];
    float r0 = fmaxf(fmaf(a0 + b0, nd, bb.x), 0.0f);
    float r1 = fmaxf(fmaf(a1 + b1, nd, bb.y), 0.0f);
    int g = load_idx(gid, warp, g_flag_gid);
    atomicAdd(&out[(size_t)g * 64 + lane * 2],     r0);
    atomicAdd(&out[(size_t)g * 64 + lane * 2 + 1], r1);
}

// ------- GEMM: half_out = epilogue(m @ W + b); R rows/thread, k by 4 ---------
// INH: input rows are fp16 (layer-3 transform-first); else fp32.
// EPI==1: v = relu(acc + b) * norm_src[n];  EPI==0: v = acc.
template <int DIN, int DOUT, int R, int EPI, int INH>
__global__ void gemm_kernel(const void* __restrict__ min,
                            const float* __restrict__ W,
                            const float* __restrict__ b,
                            __half* __restrict__ out) {
    constexpr int TY  = 256 / DOUT;
    constexpr int NPB = TY * R;
    constexpr int K4  = DIN / 4;
    __shared__ float4 sm[NPB * K4];
    int tx = threadIdx.x;            // output feature
    int ty = threadIdx.y;
    int tid = ty * DOUT + tx;
    size_t base = (size_t)blockIdx.x * NPB;

    if (INH) {
        const uint2* src = (const uint2*)((const __half*)min + base * DIN);
#pragma unroll
        for (int i = tid; i < NPB * K4; i += 256) {
            uint2 u = src[i];
            float2 fa = __half22float2(*(__half2*)&u.x);
            float2 fb = __half22float2(*(__half2*)&u.y);
            sm[i] = make_float4(fa.x, fa.y, fb.x, fb.y);
        }
    } else {
        const float4* src = (const float4*)min + base * K4;
#pragma unroll
        for (int i = tid; i < NPB * K4; i += 256) sm[i] = src[i];
    }
    __syncthreads();

    float bias = EPI ? b[tx] : 0.0f;
    float acc[R];
#pragma unroll
    for (int r = 0; r < R; r++) acc[r] = bias;

#pragma unroll 4
    for (int k4 = 0; k4 < K4; k4++) {
        int k = k4 * 4;
        float w0 = W[(k + 0) * DOUT + tx];
        float w1 = W[(k + 1) * DOUT + tx];
        float w2 = W[(k + 2) * DOUT + tx];
        float w3 = W[(k + 3) * DOUT + tx];
#pragma unroll
        for (int r = 0; r < R; r++) {
            float4 v = sm[(ty * R + r) * K4 + k4];
            acc[r] = fmaf(v.x, w0, acc[r]);
            acc[r] = fmaf(v.y, w1, acc[r]);
            acc[r] = fmaf(v.z, w2, acc[r]);
            acc[r] = fmaf(v.w, w3, acc[r]);
        }
    }

#pragma unroll
    for (int r = 0; r < R; r++) {
        size_t n = base + ty * R + r;
        float v = acc[r];
        if (EPI) v = fmaxf(v, 0.0f) * g_norm_src[n];
        out[n * DOUT + tx] = __float2half_rn(v);
    }
}

// ---------------- launch ------------------------------------------------------
extern "C" void kernel_launch(void* const* d_in, const int* in_sizes, int n_in,
                              void* d_out, int out_size) {
    const float* h        = (const float*)d_in[0];
    const void*  src      = d_in[1];
    const void*  dst      = d_in[2];
    const void*  graph_id = d_in[3];
    const float* W1 = (const float*)d_in[4];
    const float* b1 = (const float*)d_in[5];
    const float* W2 = (const float*)d_in[6];
    const float* b2 = (const float*)d_in[7];
    const float* W3 = (const float*)d_in[8];
    const float* b3 = (const float*)d_in[9];
    float* out = (float*)d_out;

    __half *pH1, *pH2;
    float  *pA;
    cudaGetSymbolAddress((void**)&pH1, g_h1);
    cudaGetSymbolAddress((void**)&pH2, g_h2);
    cudaGetSymbolAddress((void**)&pA,  g_bufA);

    // setup: init (+dtype detect), degrees, scan+norms, CSR fill
    init_kernel<<<(N_NODES + 255) / 256, 256>>>((const unsigned*)src,
                                                (const unsigned*)graph_id);
    deg_kernel<<<2048, 256>>>(src, dst);
    scan_norm_kernel<<<1, 1024>>>();
    fill_csr_kernel<<<2048, 256>>>(src, dst);

    const int GATHER_GRID = (N_NODES + 7) / 8;     // 8 warps/block

    // layer 1: prescale(h)->H1 fp16, gather64 H1->A fp32, gemm 64->128 ->H2
    prescale_kernel<<<(N_NODES * 32 + 255) / 256, 256>>>(h);
    gather64h_kernel<<<GATHER_GRID, 256>>>(pH1, pA);
    {
        dim3 blk(128, 2);   // NPB = 16
        gemm_kernel<64, 128, 8, 1, 0><<<N_NODES / 16, blk>>>(pA, W1, b1, pH2);
    }

    // layer 2: gather128 H2->A, gemm 128->128 ->H1
    gather128h_kernel<<<GATHER_GRID, 256>>>(pH2, pA);
    {
        dim3 blk(128, 2);   // NPB = 16
        gemm_kernel<128, 128, 8, 1, 0><<<N_NODES / 16, blk>>>(pA, W2, b2, pH1);
    }

    // layer 3: transform first (gemm 128->64 from fp16 H1, no epi) ->H2,
    // then gather+relu+pool
    {
        dim3 blk(64, 4);    // NPB = 32
        gemm_kernel<128, 64, 8, 0, 1><<<N_NODES / 32, blk>>>(pH1, W3, nullptr, pH2);
    }
    zero_out_kernel<<<(N_GRAPHS * 64 + 255) / 256, 256>>>(out, N_GRAPHS * 64);
    gather_pool_kernel<<<(N_NODES + 7) / 8, 256>>>(pH2, b3, graph_id, out);
}

// round 11
// speedup vs baseline: 1.1825x; 1.1376x over previous
#include <cuda_runtime.h>
#include <cuda_fp16.h>
#include <mma.h>
#include <stdint.h>

using namespace nvcuda;

#define N_NODES 100000
#define N_EDGES 1600000
#define N_GRAPHS 256

// ---------------- scratch (no allocation allowed -> device globals) ----------
__device__ int    g_deg_out[N_NODES];
__device__ int    g_deg_in[N_NODES];
__device__ float  g_norm_src[N_NODES];
__device__ float  g_norm_dst[N_NODES];
__device__ int    g_row[N_NODES + 1];           // CSR row offsets (by dst)
__device__ int    g_cur[N_NODES];               // fill cursors
__device__ int    g_csr[N_EDGES];               // src index per CSR slot
__device__ __half g_hA[(size_t)N_NODES * 128];  // fp16 feature buffer A
__device__ __half g_hB[(size_t)N_NODES * 128];  // fp16 feature buffer B
__device__ __half g_w1h[64 * 128];              // fp16 weights
__device__ __half g_w2h[128 * 128];
__device__ __half g_w3h[128 * 64];
__device__ int    g_flag_idx;                   // 1 = src/dst are int32
__device__ int    g_flag_gid;                   // 1 = graph_id is int32

// ---------------- helpers ----------------------------------------------------
__device__ __forceinline__ int load_idx(const void* p, long long i, int is32) {
    if (is32) return ((const int*)p)[i];
    return (int)(((const long long*)p)[i]);
}

// init: zero degree arrays; block 0 additionally does dtype detection.
// int64 values < 2^31 -> every odd 32-bit word is 0; int32 data -> nonzero.
// src: head window (random values => certain nonzero if int32).
// gid: TAIL window (sorted ascending; head is legitimately zero either way).
__global__ void init_kernel(const unsigned* __restrict__ s,
                            const unsigned* __restrict__ g) {
    int i = blockIdx.x * blockDim.x + threadIdx.x;
    if (i == 0) { g_flag_idx = 0; g_flag_gid = 0; }
    if (i < N_NODES) { g_deg_out[i] = 0; g_deg_in[i] = 0; }
    if (blockIdx.x == 0) {
        int fi = 0, fg = 0;
        for (int j = threadIdx.x; j < 2048; j += 256)
            if ((j & 1) && s[j]) fi = 1;
        for (int j = N_NODES - 2048 + threadIdx.x; j < N_NODES; j += 256)
            if ((j & 1) && g[j]) fg = 1;
        if (fi) g_flag_idx = 1;
        if (fg) g_flag_gid = 1;
    }
}

__global__ void zero_out_kernel(float* p, int n) {
    int i = blockIdx.x * blockDim.x + threadIdx.x;
    if (i < n) p[i] = 0.0f;
}

// convert all three weight matrices to fp16 once
__global__ void wconv_kernel(const float* __restrict__ W1,
                             const float* __restrict__ W2,
                             const float* __restrict__ W3) {
    int i = blockIdx.x * blockDim.x + threadIdx.x;
    if (i < 64 * 128)  g_w1h[i] = __float2half_rn(W1[i]);
    if (i < 128 * 128) g_w2h[i] = __float2half_rn(W2[i]);
    if (i < 128 * 64)  g_w3h[i] = __float2half_rn(W3[i]);
}

// ---------------- degrees ----------------------------------------------------
__global__ void deg_kernel(const void* src, const void* dst) {
    int is32 = g_flag_idx;
    long long i = (long long)blockIdx.x * blockDim.x + threadIdx.x;
    long long stride = (long long)gridDim.x * blockDim.x;
    for (; i < N_EDGES; i += stride) {
        atomicAdd(&g_deg_out[load_idx(src, i, is32)], 1);
        atomicAdd(&g_deg_in[load_idx(dst, i, is32)], 1);
    }
}

// single-block: exclusive scan of deg_in -> row offsets/cursors, plus norms
__global__ void scan_norm_kernel() {
    __shared__ int ssum[1024];
    const int CH = (N_NODES + 1023) / 1024;   // 98
    int t = threadIdx.x;
    int lo = t * CH;
    int hi = min(lo + CH, N_NODES);
    int s = 0;
    for (int i = lo; i < hi; i++) {
        int di = g_deg_in[i];
        int doo = g_deg_out[i];
        s += di;
        g_norm_src[i] = (doo > 0) ? rsqrtf((float)doo) : 0.0f;
        g_norm_dst[i] = (di  > 0) ? rsqrtf((float)di)  : 0.0f;
    }
    ssum[t] = s;
    __syncthreads();
    for (int off = 1; off < 1024; off <<= 1) {
        int v = (t >= off) ? ssum[t - off] : 0;
        __syncthreads();
        ssum[t] += v;
        __syncthreads();
    }
    int run = (t > 0) ? ssum[t - 1] : 0;
    for (int i = lo; i < hi; i++) {
        g_row[i] = run;
        g_cur[i] = run;
        run += g_deg_in[i];
    }
    if (t == 1023) g_row[N_NODES] = ssum[1023];
}

__global__ void fill_csr_kernel(const void* src, const void* dst) {
    int is32 = g_flag_idx;
    long long i = (long long)blockIdx.x * blockDim.x + threadIdx.x;
    long long stride = (long long)gridDim.x * blockDim.x;
    for (; i < N_EDGES; i += stride) {
        int d = load_idx(dst, i, is32);
        int pos = atomicAdd(&g_cur[d], 1);
        g_csr[pos] = load_idx(src, i, is32);
    }
}

// ------ prescale: g_hA = fp16(h * norm_src), row-major 64/node ---------------
__global__ void prescale_kernel(const float* __restrict__ h) {
    int i = blockIdx.x * blockDim.x + threadIdx.x;   // over N_NODES*32 half2
    if (i >= N_NODES * 32) return;
    int n = i >> 5;
    float ns = g_norm_src[n];
    float2 v = ((const float2*)h)[i];
    v.x *= ns; v.y *= ns;
    ((__half2*)g_hA)[i] = __float22half2_rn(v);
}

// ------- CSR gather (64-dim fp16 -> fp16), 2-edge pipelined ------------------
__global__ void gather64h_kernel(const __half* __restrict__ x,
                                 __half* __restrict__ out) {
    int warp = (blockIdx.x << 3) | (threadIdx.x >> 5);
    int lane = threadIdx.x & 31;
    if (warp >= N_NODES) return;
    int lo = g_row[warp], hi = g_row[warp + 1];
    float a0 = 0.f, a1 = 0.f, b0 = 0.f, b1 = 0.f;
    int j = lo;
    for (; j + 1 < hi; j += 2) {
        int s0 = g_csr[j], s1 = g_csr[j + 1];
        unsigned u0 = ((const unsigned*)(x + (size_t)s0 * 64))[lane];
        unsigned u1 = ((const unsigned*)(x + (size_t)s1 * 64))[lane];
        float2 v0 = __half22float2(*(__half2*)&u0);
        float2 v1 = __half22float2(*(__half2*)&u1);
        a0 += v0.x; a1 += v0.y;
        b0 += v1.x; b1 += v1.y;
    }
    if (j < hi) {
        int s0 = g_csr[j];
        unsigned u0 = ((const unsigned*)(x + (size_t)s0 * 64))[lane];
        float2 v0 = __half22float2(*(__half2*)&u0);
        a0 += v0.x; a1 += v0.y;
    }
    float nd = g_norm_dst[warp];
    float2 r; r.x = (a0 + b0) * nd; r.y = (a1 + b1) * nd;
    ((__half2*)(out + (size_t)warp * 64))[lane] = __float22half2_rn(r);
}

// ------- CSR gather (128-dim fp16 -> fp16), 2-edge pipelined -----------------
__global__ void gather128h_kernel(const __half* __restrict__ x,
                                  __half* __restrict__ out) {
    int warp = (blockIdx.x << 3) | (threadIdx.x >> 5);
    int lane = threadIdx.x & 31;
    if (warp >= N_NODES) return;
    int lo = g_row[warp], hi = g_row[warp + 1];
    float a0=0.f,a1=0.f,a2=0.f,a3=0.f,b0=0.f,b1=0.f,b2=0.f,b3=0.f;
    int j = lo;
    for (; j + 1 < hi; j += 2) {
        int s0 = g_csr[j], s1 = g_csr[j + 1];
        uint2 u0 = ((const uint2*)(x + (size_t)s0 * 128))[lane];
        uint2 u1 = ((const uint2*)(x + (size_t)s1 * 128))[lane];
        float2 v0a = __half22float2(*(__half2*)&u0.x);
        float2 v0b = __half22float2(*(__half2*)&u0.y);
        float2 v1a = __half22float2(*(__half2*)&u1.x);
        float2 v1b = __half22float2(*(__half2*)&u1.y);
        a0 += v0a.x; a1 += v0a.y; a2 += v0b.x; a3 += v0b.y;
        b0 += v1a.x; b1 += v1a.y; b2 += v1b.x; b3 += v1b.y;
    }
    if (j < hi) {
        int s0 = g_csr[j];
        uint2 u0 = ((const uint2*)(x + (size_t)s0 * 128))[lane];
        float2 v0a = __half22float2(*(__half2*)&u0.x);
        float2 v0b = __half22float2(*(__half2*)&u0.y);
        a0 += v0a.x; a1 += v0a.y; a2 += v0b.x; a3 += v0b.y;
    }
    float nd = g_norm_dst[warp];
    __half2 p0 = __float22half2_rn(make_float2((a0 + b0) * nd, (a1 + b1) * nd));
    __half2 p1 = __float22half2_rn(make_float2((a2 + b2) * nd, (a3 + b3) * nd));
    uint2 u; u.x = *(unsigned*)&p0; u.y = *(unsigned*)&p1;
    ((uint2*)(out + (size_t)warp * 128))[lane] = u;
}

// final layer gather (fp16 rows): relu(acc*nd + b3) then pooled atomicAdd
__global__ void gather_pool_kernel(const __half* __restrict__ x,
                                   const float* __restrict__ b3,
                                   const void* __restrict__ gid,
                                   float* __restrict__ out) {
    int warp = (blockIdx.x << 3) | (threadIdx.x >> 5);
    int lane = threadIdx.x & 31;
    if (warp >= N_NODES) return;
    int lo = g_row[warp], hi = g_row[warp + 1];
    float a0 = 0.f, a1 = 0.f, b0 = 0.f, b1 = 0.f;
    int j = lo;
    for (; j + 1 < hi; j += 2) {
        int s0 = g_csr[j], s1 = g_csr[j + 1];
        unsigned u0 = ((const unsigned*)(x + (size_t)s0 * 64))[lane];
        unsigned u1 = ((const unsigned*)(x + (size_t)s1 * 64))[lane];
        float2 v0 = __half22float2(*(__half2*)&u0);
        float2 v1 = __half22float2(*(__half2*)&u1);
        a0 += v0.x; a1 += v0.y;
        b0 += v1.x; b1 += v1.y;
    }
    if (j < hi) {
        int s0 = g_csr[j];
        unsigned u0 = ((const unsigned*)(x + (size_t)s0 * 64))[lane];
        float2 v0 = __half22float2(*(__half2*)&u0);
        a0 += v0.x; a1 += v0.y;
    }
    float nd = g_norm_dst[warp];
    float2 bb = ((const float2*)b3)[lane];
    float r0 = fmaxf(fmaf(a0 + b0, nd, bb.x), 0.0f);
    float r1 = fmaxf(fmaf(a1 + b1, nd, bb.y), 0.0f);
    int g = load_idx(gid, warp, g_flag_gid);
    atomicAdd(&out[(size_t)g * 64 + lane * 2],     r0);
    atomicAdd(&out[(size_t)g * 64 + lane * 2 + 1], r1);
}

// ------- tensor-core GEMM: out = epilogue(A @ Bh + bias), fp16 in/out --------
// A: [N_NODES, DIN] fp16 row-major.  Bh: [DIN, DOUT] fp16 row-major.
// EPI==1: v = relu(acc + bias[col]) * norm_src[row];  EPI==0: v = acc.
// 8 warps/block; exact tiling (N_NODES % M_TILE == 0).
template <int DIN, int DOUT, int M_TILE, int EPI>
__global__ void wmma_gemm_kernel(const __half* __restrict__ A,
                                 const __half* __restrict__ Bh,
                                 const float* __restrict__ bias,
                                 __half* __restrict__ out) {
    constexpr int N_T = DOUT / 16;          // n tiles
    constexpr int WPN = 8 / N_T;            // warps per n tile
    constexpr int MF  = (M_TILE / 16) / WPN;// m fragments per warp (=5)
    __shared__ float scratch[8][16 * 16];
    int w    = threadIdx.x >> 5;
    int lane = threadIdx.x & 31;
    int n_tile = w / WPN;
    int m0     = (w % WPN) * MF;
    size_t base = (size_t)blockIdx.x * M_TILE;

    wmma::fragment<wmma::accumulator, 16, 16, 16, float> acc[MF];
#pragma unroll
    for (int m = 0; m < MF; m++) wmma::fill_fragment(acc[m], 0.0f);

    wmma::fragment<wmma::matrix_a, 16, 16, 16, __half, wmma::row_major> afrag;
    wmma::fragment<wmma::matrix_b, 16, 16, 16, __half, wmma::row_major> bfrag;

#pragma unroll
    for (int k = 0; k < DIN / 16; k++) {
        wmma::load_matrix_sync(bfrag, Bh + (size_t)(k * 16) * DOUT + n_tile * 16, DOUT);
#pragma unroll
        for (int m = 0; m < MF; m++) {
            wmma::load_matrix_sync(afrag, A + (base + (size_t)(m0 + m) * 16) * DIN + k * 16, DIN);
            wmma::mma_sync(acc[m], afrag, bfrag, acc[m]);
        }
    }

#pragma unroll
    for (int m = 0; m < MF; m++) {
        wmma::store_matrix_sync(scratch[w], acc[m], 16, wmma::mem_row_major);
        __syncwarp();
#pragma unroll
        for (int e = lane; e < 256; e += 32) {
            int r = e >> 4, c = e & 15;
            size_t row = base + (size_t)(m0 + m) * 16 + r;
            int col = n_tile * 16 + c;
            float v = scratch[w][e];
            if (EPI) v = fmaxf(v + bias[col], 0.0f) * g_norm_src[row];
            out[row * DOUT + col] = __float2half_rn(v);
        }
        __syncwarp();
    }
}

// ---------------- launch ------------------------------------------------------
extern "C" void kernel_launch(void* const* d_in, const int* in_sizes, int n_in,
                              void* d_out, int out_size) {
    const float* h        = (const float*)d_in[0];
    const void*  src      = d_in[1];
    const void*  dst      = d_in[2];
    const void*  graph_id = d_in[3];
    const float* W1 = (const float*)d_in[4];
    const float* b1 = (const float*)d_in[5];
    const float* W2 = (const float*)d_in[6];
    const float* b2 = (const float*)d_in[7];
    const float* W3 = (const float*)d_in[8];
    const float* b3 = (const float*)d_in[9];
    float* out = (float*)d_out;

    __half *pA, *pB, *pW1, *pW2, *pW3;
    cudaGetSymbolAddress((void**)&pA,  g_hA);
    cudaGetSymbolAddress((void**)&pB,  g_hB);
    cudaGetSymbolAddress((void**)&pW1, g_w1h);
    cudaGetSymbolAddress((void**)&pW2, g_w2h);
    cudaGetSymbolAddress((void**)&pW3, g_w3h);

    // setup: init (+dtype detect), degrees, scan+norms, CSR fill, W->fp16
    init_kernel<<<(N_NODES + 255) / 256, 256>>>((const unsigned*)src,
                                                (const unsigned*)graph_id);
    deg_kernel<<<2048, 256>>>(src, dst);
    scan_norm_kernel<<<1, 1024>>>();
    fill_csr_kernel<<<2048, 256>>>(src, dst);
    wconv_kernel<<<(128 * 128 + 255) / 256, 256>>>(W1, W2, W3);

    const int GATHER_GRID = (N_NODES + 7) / 8;     // 8 warps/block

    // layer 1: prescale(h)->A(64), gather64 A->B(64), wmma 64->128 B->A
    prescale_kernel<<<(N_NODES * 32 + 255) / 256, 256>>>(h);
    gather64h_kernel<<<GATHER_GRID, 256>>>(pA, pB);
    wmma_gemm_kernel<64, 128, 80, 1><<<N_NODES / 80, 256>>>(pB, pW1, b1, pA);

    // layer 2: gather128 A->B, wmma 128->128 B->A
    gather128h_kernel<<<GATHER_GRID, 256>>>(pA, pB);
    wmma_gemm_kernel<128, 128, 80, 1><<<N_NODES / 80, 256>>>(pB, pW2, b2, pA);

    // layer 3: transform first (wmma 128->64, no epi) A->B, then gather+pool
    wmma_gemm_kernel<128, 64, 160, 0><<<N_NODES / 160, 256>>>(pA, pW3, nullptr, pB);
    zero_out_kernel<<<(N_GRAPHS * 64 + 255) / 256, 256>>>(out, N_GRAPHS * 64);
    gather_pool_kernel<<<(N_NODES + 7) / 8, 256>>>(pB, b3, graph_id, out);
}

// round 12
// speedup vs baseline: 2.1495x; 1.8177x over previous
#include <cuda_runtime.h>
#include <cuda_fp16.h>
#include <mma.h>
#include <stdint.h>

using namespace nvcuda;

#define N_NODES 100000
#define N_EDGES 1600000
#define N_GRAPHS 256
#define SCAN_BLOCKS 100
#define SCAN_CHUNK 1000   // N_NODES = SCAN_BLOCKS * SCAN_CHUNK exactly

// ---------------- scratch (no allocation allowed -> device globals) ----------
__device__ int    g_deg_out[N_NODES];
__device__ int    g_deg_in[N_NODES];
__device__ float  g_norm_src[N_NODES];
__device__ float  g_norm_dst[N_NODES];
__device__ int    g_row[N_NODES + 1];           // CSR row offsets (by dst)
__device__ int    g_cur[N_NODES];               // fill cursors
__device__ int    g_csr[N_EDGES];               // src index per CSR slot
__device__ int    g_blk[SCAN_BLOCKS];           // per-block degree sums
__device__ __half g_hA[(size_t)N_NODES * 128];  // fp16 feature buffer A
__device__ __half g_hB[(size_t)N_NODES * 128];  // fp16 feature buffer B
__device__ __half g_w1h[64 * 128];              // fp16 weights
__device__ __half g_w2h[128 * 128];
__device__ __half g_w3h[128 * 64];
__device__ int    g_flag_idx;                   // 1 = src/dst are int32
__device__ int    g_flag_gid;                   // 1 = graph_id is int32

// ---------------- helpers ----------------------------------------------------
__device__ __forceinline__ int load_idx(const void* p, long long i, int is32) {
    if (is32) return ((const int*)p)[i];
    return (int)(((const long long*)p)[i]);
}

// init: zero degree arrays; block 0 additionally does dtype detection.
// int64 values < 2^31 -> every odd 32-bit word is 0; int32 data -> nonzero.
// src: head window (random values => certain nonzero if int32).
// gid: TAIL window (sorted ascending; head is legitimately zero either way).
__global__ void init_kernel(const unsigned* __restrict__ s,
                            const unsigned* __restrict__ g) {
    int i = blockIdx.x * blockDim.x + threadIdx.x;
    if (i == 0) { g_flag_idx = 0; g_flag_gid = 0; }
    if (i < N_NODES) { g_deg_out[i] = 0; g_deg_in[i] = 0; }
    if (blockIdx.x == 0) {
        int fi = 0, fg = 0;
        for (int j = threadIdx.x; j < 2048; j += 256)
            if ((j & 1) && s[j]) fi = 1;
        for (int j = N_NODES - 2048 + threadIdx.x; j < N_NODES; j += 256)
            if ((j & 1) && g[j]) fg = 1;
        if (fi) g_flag_idx = 1;
        if (fg) g_flag_gid = 1;
    }
}

__global__ void zero_out_kernel(float* p, int n) {
    int i = blockIdx.x * blockDim.x + threadIdx.x;
    if (i < n) p[i] = 0.0f;
}

// convert all three weight matrices to fp16 once
__global__ void wconv_kernel(const float* __restrict__ W1,
                             const float* __restrict__ W2,
                             const float* __restrict__ W3) {
    int i = blockIdx.x * blockDim.x + threadIdx.x;
    if (i < 64 * 128)  g_w1h[i] = __float2half_rn(W1[i]);
    if (i < 128 * 128) g_w2h[i] = __float2half_rn(W2[i]);
    if (i < 128 * 64)  g_w3h[i] = __float2half_rn(W3[i]);
}

// ---------------- degrees ----------------------------------------------------
__global__ void deg_kernel(const void* src, const void* dst) {
    int is32 = g_flag_idx;
    long long i = (long long)blockIdx.x * blockDim.x + threadIdx.x;
    long long stride = (long long)gridDim.x * blockDim.x;
    for (; i < N_EDGES; i += stride) {
        atomicAdd(&g_deg_out[load_idx(src, i, is32)], 1);
        atomicAdd(&g_deg_in[load_idx(dst, i, is32)], 1);
    }
}

// scan stage A: per-block degree sums + norms (SCAN_BLOCKS blocks, 1024 thr)
__global__ void scanA_kernel() {
    __shared__ int ssum[1024];
    int b = blockIdx.x;
    int t = threadIdx.x;
    int i = b * SCAN_CHUNK + t;
    int d = 0;
    if (t < SCAN_CHUNK) {
        d = g_deg_in[i];
        int doo = g_deg_out[i];
        g_norm_src[i] = (doo > 0) ? rsqrtf((float)doo) : 0.0f;
        g_norm_dst[i] = (d   > 0) ? rsqrtf((float)d)   : 0.0f;
    }
    ssum[t] = d;
    __syncthreads();
    for (int off = 512; off > 0; off >>= 1) {
        if (t < off) ssum[t] += ssum[t + off];
        __syncthreads();
    }
    if (t == 0) g_blk[b] = ssum[0];
}

// scan stage B: every block scans the 100 partials + its local 1000 elements
__global__ void scanB_kernel() {
    __shared__ int sblk[128];
    __shared__ int sdeg[1024];
    int b = blockIdx.x;
    int t = threadIdx.x;

    // scan block partials (inclusive over 128, padded)
    if (t < 128) sblk[t] = (t < SCAN_BLOCKS) ? g_blk[t] : 0;
    __syncthreads();
    for (int off = 1; off < 128; off <<= 1) {
        int v = (t >= off && t < 128) ? sblk[t - off] : 0;
        __syncthreads();
        if (t < 128) sblk[t] += v;
        __syncthreads();
    }
    int blk_off = (b > 0) ? sblk[b - 1] : 0;

    // local inclusive scan of this block's SCAN_CHUNK degrees (padded to 1024)
    int i = b * SCAN_CHUNK + t;
    int d = (t < SCAN_CHUNK) ? g_deg_in[i] : 0;
    sdeg[t] = d;
    __syncthreads();
    for (int off = 1; off < 1024; off <<= 1) {
        int v = (t >= off) ? sdeg[t - off] : 0;
        __syncthreads();
        sdeg[t] += v;
        __syncthreads();
    }
    if (t < SCAN_CHUNK) {
        int excl = blk_off + sdeg[t] - d;
        g_row[i] = excl;
        g_cur[i] = excl;
        if (b == SCAN_BLOCKS - 1 && t == SCAN_CHUNK - 1)
            g_row[N_NODES] = blk_off + sdeg[t];
    }
}

__global__ void fill_csr_kernel(const void* src, const void* dst) {
    int is32 = g_flag_idx;
    long long i = (long long)blockIdx.x * blockDim.x + threadIdx.x;
    long long stride = (long long)gridDim.x * blockDim.x;
    for (; i < N_EDGES; i += stride) {
        int d = load_idx(dst, i, is32);
        int pos = atomicAdd(&g_cur[d], 1);
        g_csr[pos] = load_idx(src, i, is32);
    }
}

// ------ prescale: g_hA = fp16(h * norm_src), row-major 64/node ---------------
__global__ void prescale_kernel(const float* __restrict__ h) {
    int i = blockIdx.x * blockDim.x + threadIdx.x;   // over N_NODES*32 half2
    if (i >= N_NODES * 32) return;
    int n = i >> 5;
    float ns = g_norm_src[n];
    float2 v = ((const float2*)h)[i];
    v.x *= ns; v.y *= ns;
    ((__half2*)g_hA)[i] = __float22half2_rn(v);
}

// ------- CSR gather (64-dim fp16), HALF-WARP per node, 2-edge pipelined ------
// 16 lanes x uint2 (8B) = 128B row; each warp serves 2 nodes concurrently.
__global__ void gather64h_kernel(const __half* __restrict__ x,
                                 __half* __restrict__ out) {
    int gid  = blockIdx.x * blockDim.x + threadIdx.x;
    int node = gid >> 4;
    int lane = gid & 15;
    if (node >= N_NODES) return;
    int lo = g_row[node], hi = g_row[node + 1];
    float a0=0.f,a1=0.f,a2=0.f,a3=0.f,b0=0.f,b1=0.f,b2=0.f,b3=0.f;
    int j = lo;
    for (; j + 1 < hi; j += 2) {
        int s0 = g_csr[j], s1 = g_csr[j + 1];
        uint2 u0 = ((const uint2*)(x + (size_t)s0 * 64))[lane];
        uint2 u1 = ((const uint2*)(x + (size_t)s1 * 64))[lane];
        float2 p0 = __half22float2(*(__half2*)&u0.x);
        float2 p1 = __half22float2(*(__half2*)&u0.y);
        float2 q0 = __half22float2(*(__half2*)&u1.x);
        float2 q1 = __half22float2(*(__half2*)&u1.y);
        a0 += p0.x; a1 += p0.y; a2 += p1.x; a3 += p1.y;
        b0 += q0.x; b1 += q0.y; b2 += q1.x; b3 += q1.y;
    }
    if (j < hi) {
        int s0 = g_csr[j];
        uint2 u0 = ((const uint2*)(x + (size_t)s0 * 64))[lane];
        float2 p0 = __half22float2(*(__half2*)&u0.x);
        float2 p1 = __half22float2(*(__half2*)&u0.y);
        a0 += p0.x; a1 += p0.y; a2 += p1.x; a3 += p1.y;
    }
    float nd = g_norm_dst[node];
    __half2 r0 = __float22half2_rn(make_float2((a0 + b0) * nd, (a1 + b1) * nd));
    __half2 r1 = __float22half2_rn(make_float2((a2 + b2) * nd, (a3 + b3) * nd));
    uint2 o; o.x = *(unsigned*)&r0; o.y = *(unsigned*)&r1;
    ((uint2*)(out + (size_t)node * 64))[lane] = o;
}

// ------- CSR gather (128-dim fp16), HALF-WARP per node, 2-edge pipelined -----
// 16 lanes x uint4 (16B) = 256B row.
__global__ void gather128h_kernel(const __half* __restrict__ x,
                                  __half* __restrict__ out) {
    int gid  = blockIdx.x * blockDim.x + threadIdx.x;
    int node = gid >> 4;
    int lane = gid & 15;
    if (node >= N_NODES) return;
    int lo = g_row[node], hi = g_row[node + 1];
    float a[8] = {0,0,0,0,0,0,0,0};
    float b[8] = {0,0,0,0,0,0,0,0};
    int j = lo;
    for (; j + 1 < hi; j += 2) {
        int s0 = g_csr[j], s1 = g_csr[j + 1];
        uint4 u0 = ((const uint4*)(x + (size_t)s0 * 128))[lane];
        uint4 u1 = ((const uint4*)(x + (size_t)s1 * 128))[lane];
        float2 p0 = __half22float2(*(__half2*)&u0.x);
        float2 p1 = __half22float2(*(__half2*)&u0.y);
        float2 p2 = __half22float2(*(__half2*)&u0.z);
        float2 p3 = __half22float2(*(__half2*)&u0.w);
        float2 q0 = __half22float2(*(__half2*)&u1.x);
        float2 q1 = __half22float2(*(__half2*)&u1.y);
        float2 q2 = __half22float2(*(__half2*)&u1.z);
        float2 q3 = __half22float2(*(__half2*)&u1.w);
        a[0] += p0.x; a[1] += p0.y; a[2] += p1.x; a[3] += p1.y;
        a[4] += p2.x; a[5] += p2.y; a[6] += p3.x; a[7] += p3.y;
        b[0] += q0.x; b[1] += q0.y; b[2] += q1.x; b[3] += q1.y;
        b[4] += q2.x; b[5] += q2.y; b[6] += q3.x; b[7] += q3.y;
    }
    if (j < hi) {
        int s0 = g_csr[j];
        uint4 u0 = ((const uint4*)(x + (size_t)s0 * 128))[lane];
        float2 p0 = __half22float2(*(__half2*)&u0.x);
        float2 p1 = __half22float2(*(__half2*)&u0.y);
        float2 p2 = __half22float2(*(__half2*)&u0.z);
        float2 p3 = __half22float2(*(__half2*)&u0.w);
        a[0] += p0.x; a[1] += p0.y; a[2] += p1.x; a[3] += p1.y;
        a[4] += p2.x; a[5] += p2.y; a[6] += p3.x; a[7] += p3.y;
    }
    float nd = g_norm_dst[node];
    __half2 r0 = __float22half2_rn(make_float2((a[0]+b[0])*nd, (a[1]+b[1])*nd));
    __half2 r1 = __float22half2_rn(make_float2((a[2]+b[2])*nd, (a[3]+b[3])*nd));
    __half2 r2 = __float22half2_rn(make_float2((a[4]+b[4])*nd, (a[5]+b[5])*nd));
    __half2 r3 = __float22half2_rn(make_float2((a[6]+b[6])*nd, (a[7]+b[7])*nd));
    uint4 o;
    o.x = *(unsigned*)&r0; o.y = *(unsigned*)&r1;
    o.z = *(unsigned*)&r2; o.w = *(unsigned*)&r3;
    ((uint4*)(out + (size_t)node * 128))[lane] = o;
}

// final layer gather (64-dim fp16), HALF-WARP per node, pooled atomicAdd ------
__global__ void gather_pool_kernel(const __half* __restrict__ x,
                                   const float* __restrict__ b3,
                                   const void* __restrict__ gid,
                                   float* __restrict__ out) {
    int g_id = blockIdx.x * blockDim.x + threadIdx.x;
    int node = g_id >> 4;
    int lane = g_id & 15;
    if (node >= N_NODES) return;
    int lo = g_row[node], hi = g_row[node + 1];
    float a0=0.f,a1=0.f,a2=0.f,a3=0.f,b0=0.f,b1=0.f,b2=0.f,b3v=0.f;
    int j = lo;
    for (; j + 1 < hi; j += 2) {
        int s0 = g_csr[j], s1 = g_csr[j + 1];
        uint2 u0 = ((const uint2*)(x + (size_t)s0 * 64))[lane];
        uint2 u1 = ((const uint2*)(x + (size_t)s1 * 64))[lane];
        float2 p0 = __half22float2(*(__half2*)&u0.x);
        float2 p1 = __half22float2(*(__half2*)&u0.y);
        float2 q0 = __half22float2(*(__half2*)&u1.x);
        float2 q1 = __half22float2(*(__half2*)&u1.y);
        a0 += p0.x; a1 += p0.y; a2 += p1.x; a3 += p1.y;
        b0 += q0.x; b1 += q0.y; b2 += q1.x; b3v += q1.y;
    }
    if (j < hi) {
        int s0 = g_csr[j];
        uint2 u0 = ((const uint2*)(x + (size_t)s0 * 64))[lane];
        float2 p0 = __half22float2(*(__half2*)&u0.x);
        float2 p1 = __half22float2(*(__half2*)&u0.y);
        a0 += p0.x; a1 += p0.y; a2 += p1.x; a3 += p1.y;
    }
    float nd = g_norm_dst[node];
    float4 bb = ((const float4*)b3)[lane];
    float r0 = fmaxf(fmaf(a0 + b0,  nd, bb.x), 0.0f);
    float r1 = fmaxf(fmaf(a1 + b1,  nd, bb.y), 0.0f);
    float r2 = fmaxf(fmaf(a2 + b2,  nd, bb.z), 0.0f);
    float r3 = fmaxf(fmaf(a3 + b3v, nd, bb.w), 0.0f);
    int g = load_idx(gid, node, g_flag_gid);
    float* o = out + (size_t)g * 64 + lane * 4;
    atomicAdd(o + 0, r0);
    atomicAdd(o + 1, r1);
    atomicAdd(o + 2, r2);
    atomicAdd(o + 3, r3);
}

// ------- tensor-core GEMM with smem-staged A tile ----------------------------
// A: [N_NODES, DIN] fp16 row-major.  Bh: [DIN, DOUT] fp16 row-major.
// M_TILE=80, warps = DOUT/16, each warp owns one 16-col n_tile and 5 m-frags.
// EPI==1: v = relu(acc + bias[col]) * norm_src[row];  EPI==0: v = acc.
template <int DIN, int DOUT, int EPI>
__global__ void wmma_gemm_kernel(const __half* __restrict__ A,
                                 const __half* __restrict__ Bh,
                                 const float* __restrict__ bias,
                                 __half* __restrict__ out) {
    constexpr int M_TILE  = 80;
    constexpr int NWARPS  = DOUT / 16;
    constexpr int THREADS = NWARPS * 32;
    constexpr int MF      = M_TILE / 16;    // 5 m-fragments per warp
    __shared__ __half As[M_TILE * DIN];
    __shared__ float scratch[NWARPS][16 * 16];
    int tid  = threadIdx.x;
    int w    = tid >> 5;
    int lane = tid & 31;
    size_t base = (size_t)blockIdx.x * M_TILE;

    // cooperative 16B-vector load of the A tile
    {
        const uint4* srcv = (const uint4*)(A + base * DIN);
        uint4* dstv = (uint4*)As;
#pragma unroll
        for (int i = tid; i < M_TILE * DIN / 8; i += THREADS) dstv[i] = srcv[i];
    }
    __syncthreads();

    wmma::fragment<wmma::accumulator, 16, 16, 16, float> acc[MF];
#pragma unroll
    for (int m = 0; m < MF; m++) wmma::fill_fragment(acc[m], 0.0f);

    wmma::fragment<wmma::matrix_a, 16, 16, 16, __half, wmma::row_major> afrag;
    wmma::fragment<wmma::matrix_b, 16, 16, 16, __half, wmma::row_major> bfrag;

#pragma unroll
    for (int k = 0; k < DIN / 16; k++) {
        wmma::load_matrix_sync(bfrag, Bh + (size_t)(k * 16) * DOUT + w * 16, DOUT);
#pragma unroll
        for (int m = 0; m < MF; m++) {
            wmma::load_matrix_sync(afrag, As + (size_t)(m * 16) * DIN + k * 16, DIN);
            wmma::mma_sync(acc[m], afrag, bfrag, acc[m]);
        }
    }

#pragma unroll
    for (int m = 0; m < MF; m++) {
        wmma::store_matrix_sync(scratch[w], acc[m], 16, wmma::mem_row_major);
        __syncwarp();
#pragma unroll
        for (int e = lane; e < 256; e += 32) {
            int r = e >> 4, c = e & 15;
            size_t row = base + (size_t)m * 16 + r;
            int col = w * 16 + c;
            float v = scratch[w][e];
            if (EPI) v = fmaxf(v + bias[col], 0.0f) * g_norm_src[row];
            out[row * DOUT + col] = __float2half_rn(v);
        }
        __syncwarp();
    }
}

// ---------------- launch ------------------------------------------------------
extern "C" void kernel_launch(void* const* d_in, const int* in_sizes, int n_in,
                              void* d_out, int out_size) {
    const float* h        = (const float*)d_in[0];
    const void*  src      = d_in[1];
    const void*  dst      = d_in[2];
    const void*  graph_id = d_in[3];
    const float* W1 = (const float*)d_in[4];
    const float* b1 = (const float*)d_in[5];
    const float* W2 = (const float*)d_in[6];
    const float* b2 = (const float*)d_in[7];
    const float* W3 = (const float*)d_in[8];
    const float* b3 = (const float*)d_in[9];
    float* out = (float*)d_out;

    __half *pA, *pB, *pW1, *pW2, *pW3;
    cudaGetSymbolAddress((void**)&pA,  g_hA);
    cudaGetSymbolAddress((void**)&pB,  g_hB);
    cudaGetSymbolAddress((void**)&pW1, g_w1h);
    cudaGetSymbolAddress((void**)&pW2, g_w2h);
    cudaGetSymbolAddress((void**)&pW3, g_w3h);

    // setup: init (+dtype detect), degrees, 2-stage scan+norms, CSR fill, W->fp16
    init_kernel<<<(N_NODES + 255) / 256, 256>>>((const unsigned*)src,
                                                (const unsigned*)graph_id);
    deg_kernel<<<2048, 256>>>(src, dst);
    scanA_kernel<<<SCAN_BLOCKS, 1024>>>();
    scanB_kernel<<<SCAN_BLOCKS, 1024>>>();
    fill_csr_kernel<<<2048, 256>>>(src, dst);
    wconv_kernel<<<(128 * 128 + 255) / 256, 256>>>(W1, W2, W3);

    const int HW_GRID = (N_NODES * 16 + 255) / 256;   // half-warp per node

    // layer 1: prescale(h)->A(64), gather64 A->B(64), wmma 64->128 B->A
    prescale_kernel<<<(N_NODES * 32 + 255) / 256, 256>>>(h);
    gather64h_kernel<<<HW_GRID, 256>>>(pA, pB);
    wmma_gemm_kernel<64, 128, 1><<<N_NODES / 80, 256>>>(pB, pW1, b1, pA);

    // layer 2: gather128 A->B, wmma 128->128 B->A
    gather128h_kernel<<<HW_GRID, 256>>>(pA, pB);
    wmma_gemm_kernel<128, 128, 1><<<N_NODES / 80, 256>>>(pB, pW2, b2, pA);

    // layer 3: transform first (wmma 128->64, no epi) A->B, then gather+pool
    wmma_gemm_kernel<128, 64, 0><<<N_NODES / 80, 128>>>(pA, pW3, nullptr, pB);
    zero_out_kernel<<<(N_GRAPHS * 64 + 255) / 256, 256>>>(out, N_GRAPHS * 64);
    gather_pool_kernel<<<HW_GRID, 256>>>(pB, b3, graph_id, out);
}